// round 17
// baseline (speedup 1.0000x reference)
#include <cuda_runtime.h>
#include <cuda_fp16.h>
#include <math.h>
#include <stdint.h>

#define TT 1024
#define HH 2880
#define II 2880
#define EE 16
#define KTOP 4
#define NROWS (TT * KTOP)
#define ALPHA 1.702f
#define LIMIT 7.0f

// fp16 GEMM tiling: BM=64, BN=160, BKH=64 halves; 2 CTAs/SM
#define BM 64
#define BN 160
#define BKH 64
#define NKT (HH / BKH)            // 45
#define A_ST (BM * 128)           // 8192 B per stage
#define B_ST (BN * 128)           // 20480 B per stage
#define STG (A_ST + B_ST)         // 28672
#define NST 4
#define SMEM_BYTES (NST * STG)    // 114688 (x2 CTAs = 229376 <= 228KB SM)

// fused converter inside GEMMs: 96 CTAs x 256 thr x 8 x 675 = 132,710,400
#define CVT_CTAS 96
#define CVT_ITERS 675

// preamble roles: blocks [0,144) w1-cvt, [144,168) x-cvt, [168,168+1024) router
#define PRE_W1_CTAS 144
#define PRE_W1_ITERS 450          // 144*256*8*450 = 132,710,400
#define PRE_X_CTAS 24
#define PRE_X_ITERS 60            // 24*256*8*60 = 2,949,120
#define PRE_BLOCKS (PRE_W1_CTAS + PRE_X_CTAS + TT)

// ---------------- scratch -----------------------------------------------
__device__ float  g_gate[(size_t)NROWS * II];
__device__ float  g_dn[(size_t)NROWS * HH];
__device__ __half g_h16[(size_t)NROWS * II];     // act output (GEMM3 A)
__device__ __half g_x16[(size_t)TT * HH];        // x in fp16
__device__ __half g_w1h[(size_t)EE * II * HH];
__device__ __half g_w3h[(size_t)EE * II * HH];
__device__ __half g_w2h[(size_t)EE * HH * II];
__device__ int    g_offs[EE + 1];
__device__ int    g_pos[NROWS];
__device__ int    g_rowtok[NROWS];
__device__ float  g_roww[NROWS];
__device__ int    g_tidx[NROWS];
__device__ float  g_tw[NROWS];

// ---------------- helpers -----------------------------------------------
__device__ __forceinline__ unsigned pack_h2(float lo, float hi) {
    __half2 h = __floats2half2_rn(lo, hi);
    return *reinterpret_cast<unsigned*>(&h);
}
__device__ __forceinline__ uint32_t smem_u32(const void* p) {
    uint32_t a;
    asm("{ .reg .u64 t; cvta.to.shared.u64 t, %1; cvt.u32.u64 %0, t; }" : "=r"(a) : "l"(p));
    return a;
}
__device__ __forceinline__ uint32_t SWZ(uint32_t off) {
    return off ^ ((off >> 3) & 0x70u);
}
#define CP_ASYNC16(dst, src)                                                \
    asm volatile("cp.async.cg.shared.global [%0], [%1], 16;" ::"r"(dst), "l"(src) : "memory")
#define CP_COMMIT() asm volatile("cp.async.commit_group;" ::: "memory")
#define CP_WAIT2()  asm volatile("cp.async.wait_group 2;" ::: "memory")

__device__ __forceinline__ void ldsm4(unsigned* r, uint32_t addr) {
    asm volatile("ldmatrix.sync.aligned.m8n8.x4.shared.b16 {%0,%1,%2,%3}, [%4];"
                 : "=r"(r[0]), "=r"(r[1]), "=r"(r[2]), "=r"(r[3]) : "r"(addr));
}
__device__ __forceinline__ void ldsm2(unsigned* r, uint32_t addr) {
    asm volatile("ldmatrix.sync.aligned.m8n8.x2.shared.b16 {%0,%1}, [%2];"
                 : "=r"(r[0]), "=r"(r[1]) : "r"(addr));
}
__device__ __forceinline__ void mma16(float* d, const unsigned* a, const unsigned* b) {
    asm volatile(
        "mma.sync.aligned.m16n8k16.row.col.f32.f16.f16.f32 "
        "{%0,%1,%2,%3}, {%4,%5,%6,%7}, {%8,%9}, {%0,%1,%2,%3};"
        : "+f"(d[0]), "+f"(d[1]), "+f"(d[2]), "+f"(d[3])
        : "r"(a[0]), "r"(a[1]), "r"(a[2]), "r"(a[3]), "r"(b[0]), "r"(b[1]));
}

__device__ __forceinline__ void cvt_stream(const float* __restrict__ s,
                                           __half* __restrict__ d,
                                           int cta, int nctas, int iters) {
    const size_t stride = (size_t)nctas * 256 * 8;
    size_t i = ((size_t)cta * 256 + threadIdx.x) * 8;
#pragma unroll 4
    for (int it = 0; it < iters; ++it, i += stride) {
        float4 a = *(const float4*)(s + i);
        float4 b = *(const float4*)(s + i + 4);
        uint4 o;
        o.x = pack_h2(a.x, a.y);
        o.y = pack_h2(a.z, a.w);
        o.z = pack_h2(b.x, b.y);
        o.w = pack_h2(b.z, b.w);
        *(uint4*)((char*)d + i * 2) = o;
    }
}

// ---------------- preamble: w1-cvt + x-cvt + router in one launch --------
__global__ __launch_bounds__(256)
void preamble_kernel(const float* __restrict__ x,
                     const float* __restrict__ rw,
                     const float* __restrict__ rb,
                     const float* __restrict__ w1,
                     __half* __restrict__ w1h,
                     __half* __restrict__ x16) {
    const int bx = blockIdx.x;
    if (bx < PRE_W1_CTAS) {
        cvt_stream(w1, w1h, bx, PRE_W1_CTAS, PRE_W1_ITERS);
        return;
    }
    if (bx < PRE_W1_CTAS + PRE_X_CTAS) {
        cvt_stream(x, x16, bx - PRE_W1_CTAS, PRE_X_CTAS, PRE_X_ITERS);
        return;
    }
    // ---- router role: EXACT 128-thread arithmetic (lanes >=128 exit) ----
    const int t = bx - PRE_W1_CTAS - PRE_X_CTAS;
    const int tid = threadIdx.x;
    if (tid >= 128) return;
    float acc[EE];
#pragma unroll
    for (int e = 0; e < EE; e++) acc[e] = 0.f;
    const float* xr = x + (size_t)t * HH;
    for (int h = tid; h < HH; h += 128) {
        float xv = xr[h];
#pragma unroll
        for (int e = 0; e < EE; e++) acc[e] = fmaf(xv, rw[e * HH + h], acc[e]);
    }
#pragma unroll
    for (int e = 0; e < EE; e++) {
#pragma unroll
        for (int o = 16; o > 0; o >>= 1) acc[e] += __shfl_xor_sync(0xffffffffu, acc[e], o);
    }
    __shared__ float sl[4][EE];
    int w = tid >> 5;
    if ((tid & 31) == 0) {
#pragma unroll
        for (int e = 0; e < EE; e++) sl[w][e] = acc[e];
    }
    __syncthreads();
    if (tid == 0) {
        float lg[EE];
        float mx = -1e30f;
#pragma unroll
        for (int e = 0; e < EE; e++) {
            lg[e] = sl[0][e] + sl[1][e] + sl[2][e] + sl[3][e] + rb[e];
            mx = fmaxf(mx, lg[e]);
        }
        float p[EE];
#pragma unroll
        for (int e = 0; e < EE; e++) p[e] = __expf(lg[e] - mx);
        bool used[EE];
#pragma unroll
        for (int e = 0; e < EE; e++) used[e] = false;
        int sel[KTOP]; float pv[KTOP]; float psum = 0.f;
        for (int k = 0; k < KTOP; k++) {
            int best = 0; float bv = -1.f;
            for (int e = 0; e < EE; e++)
                if (!used[e] && p[e] > bv) { bv = p[e]; best = e; }
            used[best] = true; sel[k] = best; pv[k] = bv; psum += bv;
        }
        float inv = 1.f / psum;
        for (int k = 0; k < KTOP; k++) {
            g_tidx[t * 4 + k] = sel[k];
            g_tw[t * 4 + k]   = pv[k] * inv;
        }
    }
}

// ---------------- deterministic grouping: 16 blocks, 1 expert each -------
__global__ void group_kernel() {
    __shared__ int cnt[EE];
    __shared__ unsigned char eid[NROWS];
    __shared__ int chunkpre[128];
    const int b = blockIdx.x;
    const int tid = threadIdx.x;
    const int warp = tid >> 5, lane = tid & 31;
    if (tid < EE) cnt[tid] = 0;
    __syncthreads();
    for (int i = tid; i < NROWS; i += 256) {
        int ev = g_tidx[i];
        eid[i] = (unsigned char)ev;
        atomicAdd(&cnt[ev], 1);
    }
    __syncthreads();
    int base = 0;
    for (int e2 = 0; e2 < b; e2++) base += cnt[e2];
    if (tid == 0) {
        g_offs[b] = base;
        if (b == EE - 1) g_offs[EE] = base + cnt[b];
    }
    for (int ch = warp; ch < 128; ch += 8) {
        bool m = (eid[ch * 32 + lane] == (unsigned char)b);
        unsigned mask = __ballot_sync(0xffffffffu, m);
        if (lane == 0) chunkpre[ch] = __popc(mask);
    }
    __syncthreads();
    if (tid == 0) {
        int s = 0;
        for (int ch = 0; ch < 128; ch++) { int c = chunkpre[ch]; chunkpre[ch] = s; s += c; }
    }
    __syncthreads();
    const unsigned lt = (lane == 0) ? 0u : (0xffffffffu >> (32 - lane));
    for (int ch = warp; ch < 128; ch += 8) {
        int i = ch * 32 + lane;
        bool m = (eid[i] == (unsigned char)b);
        unsigned mask = __ballot_sync(0xffffffffu, m);
        if (m) {
            int pos = base + chunkpre[ch] + __popc(mask & lt);
            g_pos[i] = pos;
            g_rowtok[pos] = i >> 2;
            g_roww[pos] = g_tw[i];
        }
    }
}

// ---------------- grouped GEMM + fused weight convert + fused act --------
// z==0 slice: CVT_CTAS CTAs convert cvt_src -> cvt_dst (next GEMM weights).
// z>=1: expert e = z-1 GEMM.
template<int MODE>
__global__ __launch_bounds__(256, 2)
void moe_gemm(const __half* __restrict__ Wh, const float* __restrict__ Bias,
              const float* __restrict__ cvt_src, __half* __restrict__ cvt_dst) {
    if (blockIdx.z == 0) {
        if (MODE != 2) {
            int bi = blockIdx.y * gridDim.x + blockIdx.x;
            if (bi < CVT_CTAS)
                cvt_stream(cvt_src, cvt_dst, bi, CVT_CTAS, CVT_ITERS);
        }
        return;
    }
    const int e = blockIdx.z - 1;
    const int gbase = g_offs[e];
    const int Me = g_offs[e + 1] - gbase;
    const int m0 = blockIdx.y * BM;
    if (m0 >= Me) return;
    const int n0 = blockIdx.x * BN;

    extern __shared__ char smraw[];
    const uint32_t sb = smem_u32(smraw);
    const int tid = threadIdx.x;
    const int lane = tid & 31;
    const int warp = tid >> 5;
    const int wm = warp >> 2;                  // 0..1 (M 32 each)
    const int wn = warp & 3;                   // 0..3 (N 40 each)

    float acc[2][5][4];
#pragma unroll
    for (int i = 0; i < 2; i++)
#pragma unroll
        for (int j = 0; j < 5; j++)
#pragma unroll
            for (int q = 0; q < 4; q++) acc[i][j][q] = 0.f;

    // ---- A cp.async chunks: 512 total, 2 per thread ----
    const __half* gA[2]; uint32_t sA[2];
#pragma unroll
    for (int j = 0; j < 2; j++) {
        int c = tid + j * 256;
        int row = c >> 3, kc = c & 7;
        int r = m0 + row;
        if (r >= Me) r = 0;
        const __half* rowp;
        if (MODE == 2) rowp = g_h16 + (size_t)(gbase + r) * II;
        else           rowp = g_x16 + (size_t)g_rowtok[gbase + r] * HH;
        gA[j] = rowp + kc * 8;
        sA[j] = SWZ((uint32_t)(row * 128 + kc * 16));
    }
    // ---- B cp.async chunks: 1280 total, 5 per thread ----
    const __half* gB[5]; uint32_t sB[5];
#pragma unroll
    for (int j = 0; j < 5; j++) {
        int c = tid + j * 256;
        int row = c >> 3, kc = c & 7;
        gB[j] = Wh + (size_t)e * HH * II + (size_t)(n0 + row) * HH + kc * 8;
        sB[j] = A_ST + SWZ((uint32_t)(row * 128 + kc * 16));
    }

#define ISSUE(st)                                                            \
    do {                                                                     \
        uint32_t _b = sb + ((st) & 3) * STG;                                 \
        int _k = (st) * BKH;                                                 \
        CP_ASYNC16(_b + sA[0], gA[0] + _k);                                  \
        CP_ASYNC16(_b + sA[1], gA[1] + _k);                                  \
        CP_ASYNC16(_b + sB[0], gB[0] + _k);                                  \
        CP_ASYNC16(_b + sB[1], gB[1] + _k);                                  \
        CP_ASYNC16(_b + sB[2], gB[2] + _k);                                  \
        CP_ASYNC16(_b + sB[3], gB[3] + _k);                                  \
        CP_ASYNC16(_b + sB[4], gB[4] + _k);                                  \
    } while (0)

    // ---- ldsm raw offsets + per-lane swizzle masks ----
    const uint32_t axorm = (uint32_t)((lane & 7) << 4);
    const int lane15 = lane & 15;
    const uint32_t b2xor = (uint32_t)((lane15 & 7) << 4);
    uint32_t araw[2];
#pragma unroll
    for (int mt = 0; mt < 2; mt++) {
        int R = wm * 32 + mt * 16 + (lane & 7) + ((lane >> 3) & 1) * 8;
        araw[mt] = (uint32_t)(R * 128 + ((lane >> 4) & 1) * 16);
    }
    const uint32_t braw0 = (uint32_t)(A_ST + (wn * 40 + (lane & 7) + ((lane >> 4) & 1) * 8) * 128 +
                                      ((lane >> 3) & 1) * 16);
    const uint32_t braw1 = braw0 + 16 * 128;
    const uint32_t braw2 = (uint32_t)(A_ST + (wn * 40 + 32 + (lane15 & 7)) * 128 +
                                      ((lane15 >> 3) & 1) * 16);

    unsigned af[2][4], bt0[2][4], bt1[2][4], bt2[2][2];

#define LOADA(bbase, ks)                                                     \
    do {                                                                     \
        uint32_t _o = (uint32_t)((ks) * 32);                                 \
        ldsm4(af[0], (bbase) + ((araw[0] + _o) ^ axorm));                    \
        ldsm4(af[1], (bbase) + ((araw[1] + _o) ^ axorm));                    \
    } while (0)
#define LOADB(buf, bbase, ks)                                                \
    do {                                                                     \
        uint32_t _o = (uint32_t)((ks) * 32);                                 \
        ldsm4(bt0[buf], (bbase) + ((braw0 + _o) ^ axorm));                   \
        ldsm4(bt1[buf], (bbase) + ((braw1 + _o) ^ axorm));                   \
        ldsm2(bt2[buf], (bbase) + ((braw2 + _o) ^ b2xor));                   \
    } while (0)
#define MMAS(buf)                                                            \
    do {                                                                     \
        _Pragma("unroll")                                                    \
        for (int mt = 0; mt < 2; mt++) {                                     \
            mma16(acc[mt][0], af[mt], &bt0[buf][0]);                         \
            mma16(acc[mt][1], af[mt], &bt0[buf][2]);                         \
            mma16(acc[mt][2], af[mt], &bt1[buf][0]);                         \
            mma16(acc[mt][3], af[mt], &bt1[buf][2]);                         \
            mma16(acc[mt][4], af[mt], bt2[buf]);                             \
        }                                                                    \
    } while (0)

    // ---- prologue: stages 0..2 in flight ----
    ISSUE(0); CP_COMMIT();
    ISSUE(1); CP_COMMIT();
    ISSUE(2); CP_COMMIT();

#pragma unroll 1
    for (int kt = 0; kt < NKT; ++kt) {
        CP_WAIT2();
        __syncthreads();
        if (kt + 3 < NKT) ISSUE(kt + 3);
        CP_COMMIT();

        uint32_t base = sb + (kt & 3) * STG;
        LOADB(0, base, 0);
        LOADA(base, 0); LOADB(1, base, 1); MMAS(0);
        LOADA(base, 1); LOADB(0, base, 2); MMAS(1);
        LOADA(base, 2); LOADB(1, base, 3); MMAS(0);
        LOADA(base, 3); MMAS(1);
    }

    // ---- epilogue ----
#pragma unroll
    for (int mt = 0; mt < 2; mt++) {
        int rloc0 = wm * 32 + mt * 16 + (lane >> 2);
#pragma unroll
        for (int half = 0; half < 2; half++) {
            int r = m0 + rloc0 + half * 8;
            if (r >= Me) continue;
            size_t orow = (size_t)(gbase + r) * (size_t)((MODE == 2) ? HH : II);
            if (MODE == 1) {
                const float* grow = g_gate + orow;
#pragma unroll
                for (int nt = 0; nt < 5; nt++) {
                    int col = n0 + wn * 40 + nt * 8 + (lane & 3) * 2;
                    float u0 = acc[mt][nt][half * 2 + 0] + Bias[e * HH + col];
                    float u1 = acc[mt][nt][half * 2 + 1] + Bias[e * HH + col + 1];
                    float a0 = grow[col], a1 = grow[col + 1];
                    float gg0 = fminf(a0, LIMIT);
                    float gg1 = fminf(a1, LIMIT);
                    float uu0 = fminf(fmaxf(u0, -LIMIT), LIMIT);
                    float uu1 = fminf(fmaxf(u1, -LIMIT), LIMIT);
                    float s0 = 1.f / (1.f + __expf(-ALPHA * gg0));
                    float s1 = 1.f / (1.f + __expf(-ALPHA * gg1));
                    float h0 = (uu0 + 1.f) * (gg0 * s0);
                    float h1 = (uu1 + 1.f) * (gg1 * s1);
                    *(unsigned*)((char*)g_h16 + (orow + col) * 2) = pack_h2(h0, h1);
                }
            } else {
                float* Out = (MODE == 0) ? g_gate : g_dn;
                float wgt = (MODE == 2) ? g_roww[gbase + r] : 1.f;
#pragma unroll
                for (int nt = 0; nt < 5; nt++) {
                    int col = n0 + wn * 40 + nt * 8 + (lane & 3) * 2;
                    float v0 = acc[mt][nt][half * 2 + 0] + Bias[e * HH + col];
                    float v1 = acc[mt][nt][half * 2 + 1] + Bias[e * HH + col + 1];
                    if (MODE == 2) { v0 *= wgt; v1 *= wgt; }
                    Out[orow + col]     = v0;
                    Out[orow + col + 1] = v1;
                }
            }
        }
    }
#undef ISSUE
#undef LOADA
#undef LOADB
#undef MMAS
}

// ---------------- per-token fixed-order combine -------------------------
__global__ void combine_kernel(float* __restrict__ y) {
    int t = blockIdx.x;
    const float* r0 = g_dn + (size_t)g_pos[t * 4 + 0] * HH;
    const float* r1 = g_dn + (size_t)g_pos[t * 4 + 1] * HH;
    const float* r2 = g_dn + (size_t)g_pos[t * 4 + 2] * HH;
    const float* r3 = g_dn + (size_t)g_pos[t * 4 + 3] * HH;
    float* yo = y + (size_t)t * HH;
    for (int c = threadIdx.x * 4; c < HH; c += 256 * 4) {
        float4 a = *(const float4*)(r0 + c);
        float4 b = *(const float4*)(r1 + c);
        float4 d = *(const float4*)(r2 + c);
        float4 f = *(const float4*)(r3 + c);
        *(float4*)(yo + c) = make_float4(a.x + b.x + d.x + f.x, a.y + b.y + d.y + f.y,
                                         a.z + b.z + d.z + f.z, a.w + b.w + d.w + f.w);
    }
}

// ---------------- launch ------------------------------------------------
extern "C" void kernel_launch(void* const* d_in, const int* in_sizes, int n_in,
                              void* d_out, int out_size) {
    const float* x  = (const float*)d_in[0];
    const float* rw = (const float*)d_in[1];
    const float* rb = (const float*)d_in[2];
    const float* w1 = (const float*)d_in[3];
    const float* b1 = (const float*)d_in[4];
    const float* w3 = (const float*)d_in[5];
    const float* b3 = (const float*)d_in[6];
    const float* w2 = (const float*)d_in[7];
    const float* b2 = (const float*)d_in[8];
    float* y = (float*)d_out;

    __half* x16p;  cudaGetSymbolAddress((void**)&x16p,  g_x16);
    __half* w1p;   cudaGetSymbolAddress((void**)&w1p,   g_w1h);
    __half* w3p;   cudaGetSymbolAddress((void**)&w3p,   g_w3h);
    __half* w2p;   cudaGetSymbolAddress((void**)&w2p,   g_w2h);

    cudaFuncSetAttribute(moe_gemm<0>, cudaFuncAttributeMaxDynamicSharedMemorySize, SMEM_BYTES);
    cudaFuncSetAttribute(moe_gemm<1>, cudaFuncAttributeMaxDynamicSharedMemorySize, SMEM_BYTES);
    cudaFuncSetAttribute(moe_gemm<2>, cudaFuncAttributeMaxDynamicSharedMemorySize, SMEM_BYTES);

    dim3 ggrid(HH / BN, 16, EE + 1);   // (18, 16, 17); z=0 = converter slice

    preamble_kernel<<<PRE_BLOCKS, 256>>>(x, rw, rb, w1, w1p, x16p);      // 1
    group_kernel<<<EE, 256>>>();                                         // 2
    moe_gemm<0><<<ggrid, 256, SMEM_BYTES>>>(w1p, b1, w3, w3p);           // 3
    moe_gemm<1><<<ggrid, 256, SMEM_BYTES>>>(w3p, b3, w2, w2p);           // 4
    moe_gemm<2><<<ggrid, 256, SMEM_BYTES>>>(w2p, b2, nullptr, nullptr);  // 5
    combine_kernel<<<TT, 256>>>(y);                                      // 6
}